// round 5
// baseline (speedup 1.0000x reference)
#include <cuda_runtime.h>
#include <cuda_bf16.h>
#include <cstdint>

// Problem constants
#define BB 2
#define TT 2048
#define CC 1024
#define HH 16
#define DD 64

// Scratch (device globals: allocation-free per harness rules)
__device__ float g_q[(size_t)BB * HH * TT * DD];   // (b,h,t,d)
__device__ float g_k[(size_t)BB * HH * TT * DD];
__device__ float g_v[(size_t)BB * HH * TT * DD];
__device__ float g_att[(size_t)BB * TT * CC];      // (b,t,h*D+d) attention output

// ---------------------------------------------------------------------------
// SGEMM: C = A(row-major MxK) @ B(row-major KxN) + bias
// Block tile 128x128, K-tile 8, 256 threads, 8x8 per-thread microtile,
// double-buffered shared memory.
// MODE 0: A = Ain (x), scatter output into g_q/g_k/g_v (QKV split + head reshape)
// MODE 1: A = g_att, write Out[r*N + c]
// ---------------------------------------------------------------------------
template <int Ndim, int Kdim, int MODE>
__global__ __launch_bounds__(256) void sgemm_kernel(
    const float* __restrict__ Ain, const float* __restrict__ Bm,
    const float* __restrict__ bias, float* __restrict__ Out)
{
    __shared__ __align__(16) float As[2][8][128];
    __shared__ __align__(16) float Bs[2][8][128];

    const float* __restrict__ A = (MODE == 0) ? Ain : (const float*)g_att;

    const int tid = threadIdx.x;
    const int bm = blockIdx.y;
    const int bn = blockIdx.x;
    const int tx = tid & 15;
    const int ty = tid >> 4;

    // A tile loader: 128 rows x 8 k-cols, float4 along K
    const int arow = tid >> 1;           // 0..127
    const int acol = (tid & 1) * 4;      // 0 or 4
    // B tile loader: 8 k-rows x 128 cols, float4 along N
    const int brow = tid >> 5;           // 0..7
    const int bcol = (tid & 31) * 4;     // 0..124

    const float* Aptr = A + (size_t)(bm * 128 + arow) * Kdim + acol;
    const float* Bptr = Bm + (size_t)brow * Ndim + bn * 128 + bcol;

    float acc[8][8];
#pragma unroll
    for (int i = 0; i < 8; ++i)
#pragma unroll
        for (int j = 0; j < 8; ++j) acc[i][j] = 0.f;

    // Preload tile 0
    {
        float4 ra = *(const float4*)(Aptr);
        float4 rb = *(const float4*)(Bptr);
        As[0][acol + 0][arow] = ra.x;
        As[0][acol + 1][arow] = ra.y;
        As[0][acol + 2][arow] = ra.z;
        As[0][acol + 3][arow] = ra.w;
        *(float4*)&Bs[0][brow][bcol] = rb;
    }
    __syncthreads();

    const int ktiles = Kdim / 8;
    int cur = 0;
    for (int kt = 0; kt < ktiles; ++kt) {
        float4 na, nb;
        const bool more = (kt + 1 < ktiles);
        if (more) {
            na = *(const float4*)(Aptr + (kt + 1) * 8);
            nb = *(const float4*)(Bptr + (size_t)(kt + 1) * 8 * Ndim);
        }
#pragma unroll
        for (int k = 0; k < 8; ++k) {
            float4 a0 = *(const float4*)(&As[cur][k][ty * 4]);
            float4 a1 = *(const float4*)(&As[cur][k][ty * 4 + 64]);
            float4 b0 = *(const float4*)(&Bs[cur][k][tx * 4]);
            float4 b1 = *(const float4*)(&Bs[cur][k][tx * 4 + 64]);
            float a[8] = {a0.x, a0.y, a0.z, a0.w, a1.x, a1.y, a1.z, a1.w};
            float b[8] = {b0.x, b0.y, b0.z, b0.w, b1.x, b1.y, b1.z, b1.w};
#pragma unroll
            for (int i = 0; i < 8; ++i)
#pragma unroll
                for (int j = 0; j < 8; ++j) acc[i][j] += a[i] * b[j];
        }
        if (more) {
            const int nxt = cur ^ 1;
            As[nxt][acol + 0][arow] = na.x;
            As[nxt][acol + 1][arow] = na.y;
            As[nxt][acol + 2][arow] = na.z;
            As[nxt][acol + 3][arow] = na.w;
            *(float4*)&Bs[nxt][brow][bcol] = nb;
        }
        __syncthreads();
        cur ^= 1;
    }

    // Epilogue
#pragma unroll
    for (int i = 0; i < 8; ++i) {
        const int r = bm * 128 + ty * 4 + ((i >> 2) << 6) + (i & 3);
#pragma unroll
        for (int j = 0; j < 8; ++j) {
            const int c = bn * 128 + tx * 4 + ((j >> 2) << 6) + (j & 3);
            const float v = acc[i][j] + bias[c];
            if (MODE == 0) {
                const int bidx = r >> 11;         // r / T
                const int t = r & 2047;           // r % T
                const int which = c >> 10;        // 0=q,1=k,2=v
                const int ci = c & 1023;
                const int hh = ci >> 6;
                const int dd = ci & 63;
                float* dst = (which == 0) ? g_q : ((which == 1) ? g_k : g_v);
                dst[(((size_t)bidx * HH + hh) * TT + t) * DD + dd] = v;
            } else {
                Out[(size_t)r * Ndim + c] = v;
            }
        }
    }
}

// ---------------------------------------------------------------------------
// Flash-style causal attention with ALiBi + learnable temperature.
// Grid: (T/64 q-tiles, B*H). Block: 64 threads, one query row per thread.
// q-row and O accumulator live in registers; K/V tiles staged in SMEM and
// read warp-uniform (broadcast); S row parked in SMEM scratch (same-thread
// write/read, no sync needed) to avoid local-memory spills.
// All logits kept in log2 domain (scales folded with LOG2E) -> exp2f (MUFU).
// ---------------------------------------------------------------------------
__global__ __launch_bounds__(64) void attn_kernel(const float* __restrict__ temp)
{
    __shared__ __align__(16) float Ksh[64 * 64];
    __shared__ __align__(16) float Vsh[64 * 64];
    __shared__ float Ssh[64 * 64];

    const int bh = blockIdx.y;
    const int qt = blockIdx.x;
    const int b = bh >> 4;
    const int h = bh & 15;
    const int tid = threadIdx.x;
    const int qrow = qt * 64 + tid;

    const float LOG2E = 1.44269504088896340736f;
    const float invt = 1.0f / temp[0];
    const float qscale = 0.125f * invt * LOG2E;                 // 1/sqrt(64) / temp, log2 domain
    const float slope = exp2f(-0.5f * (float)(h + 1)) * LOG2E;  // ALiBi slope_h = 2^(-(h+1)/2)

    float qr[64];
    {
        const float4* qp = (const float4*)(g_q + ((size_t)bh * TT + qrow) * DD);
#pragma unroll
        for (int i = 0; i < 16; ++i) {
            float4 f = qp[i];
            qr[4 * i + 0] = f.x * qscale;
            qr[4 * i + 1] = f.y * qscale;
            qr[4 * i + 2] = f.z * qscale;
            qr[4 * i + 3] = f.w * qscale;
        }
    }

    float o[64];
#pragma unroll
    for (int i = 0; i < 64; ++i) o[i] = 0.f;
    float m = -1e30f;
    float l = 0.f;

    float4* K4 = (float4*)Ksh;
    float4* V4 = (float4*)Vsh;

    for (int kt = 0; kt <= qt; ++kt) {
        const float4* kp = (const float4*)(g_k + ((size_t)bh * TT + kt * 64) * DD);
        const float4* vp = (const float4*)(g_v + ((size_t)bh * TT + kt * 64) * DD);
        __syncthreads();  // previous tile's V reads complete before overwrite
#pragma unroll
        for (int i = 0; i < 16; ++i) {
            K4[i * 64 + tid] = kp[i * 64 + tid];
            V4[i * 64 + tid] = vp[i * 64 + tid];
        }
        __syncthreads();

        const float base = (float)(kt * 64 - qrow);  // (key_pos - q_pos) for j=0
        const bool diag = (kt == qt);
        float tmax = -1e30f;

#pragma unroll 2
        for (int j = 0; j < 64; ++j) {
            const float4* kj = K4 + j * 16;
            float a0 = 0.f, a1 = 0.f, a2 = 0.f, a3 = 0.f;
#pragma unroll
            for (int kk = 0; kk < 16; ++kk) {
                float4 kv = kj[kk];  // warp-uniform broadcast
                a0 += qr[4 * kk + 0] * kv.x;
                a1 += qr[4 * kk + 1] * kv.y;
                a2 += qr[4 * kk + 2] * kv.z;
                a3 += qr[4 * kk + 3] * kv.w;
            }
            float sv = (a0 + a1) + (a2 + a3) + slope * (base + (float)j);
            if (diag && j > tid) sv = -1e30f;  // causal mask (only diagonal tile)
            Ssh[j * 64 + tid] = sv;
            tmax = fmaxf(tmax, sv);
        }

        const float mnew = fmaxf(m, tmax);
        const float alpha = exp2f(m - mnew);
        m = mnew;
        l *= alpha;
#pragma unroll
        for (int d = 0; d < 64; ++d) o[d] *= alpha;

#pragma unroll 2
        for (int j = 0; j < 64; ++j) {
            const float p = exp2f(Ssh[j * 64 + tid] - m);
            l += p;
            const float4* vj = V4 + j * 16;
#pragma unroll
            for (int dd = 0; dd < 16; ++dd) {
                float4 vv = vj[dd];  // warp-uniform broadcast
                o[4 * dd + 0] += p * vv.x;
                o[4 * dd + 1] += p * vv.y;
                o[4 * dd + 2] += p * vv.z;
                o[4 * dd + 3] += p * vv.w;
            }
        }
    }

    const float inv_l = 1.0f / l;
    float* op = g_att + (size_t)(b * TT + qrow) * CC + h * DD;
#pragma unroll
    for (int i = 0; i < 16; ++i) {
        float4 f;
        f.x = o[4 * i + 0] * inv_l;
        f.y = o[4 * i + 1] * inv_l;
        f.z = o[4 * i + 2] * inv_l;
        f.w = o[4 * i + 3] * inv_l;
        ((float4*)op)[i] = f;
    }
}

// ---------------------------------------------------------------------------
// Harness entry: x, W_attn, b_attn, W_proj, b_proj, temperature -> out (fp32)
// ---------------------------------------------------------------------------
extern "C" void kernel_launch(void* const* d_in, const int* in_sizes, int n_in,
                              void* d_out, int out_size)
{
    const float* x      = (const float*)d_in[0];
    const float* W_attn = (const float*)d_in[1];
    const float* b_attn = (const float*)d_in[2];
    const float* W_proj = (const float*)d_in[3];
    const float* b_proj = (const float*)d_in[4];
    const float* temp   = (const float*)d_in[5];
    float* out = (float*)d_out;

    // 1) QKV = x @ W_attn + b_attn, scattered into per-head q/k/v buffers
    sgemm_kernel<3 * CC, CC, 0><<<dim3(3 * CC / 128, BB * TT / 128), 256>>>(
        x, W_attn, b_attn, nullptr);

    // 2) Causal ALiBi attention -> g_att (B,T,C)
    attn_kernel<<<dim3(TT / 64, BB * HH), 64>>>(temp);

    // 3) out = g_att @ W_proj + b_proj
    sgemm_kernel<CC, CC, 1><<<dim3(CC / 128, BB * TT / 128), 256>>>(
        nullptr, W_proj, b_proj, out);
}

// round 7
// speedup vs baseline: 1.3114x; 1.3114x over previous
#include <cuda_runtime.h>
#include <cuda_bf16.h>
#include <cstdint>

// Problem constants
#define BB 2
#define TT 2048
#define CC 1024
#define HH 16
#define DD 64
#define MM (BB * TT)   // 4096 rows

// ---------------------------------------------------------------------------
// Device scratch (allocation-free per harness rules)
// ---------------------------------------------------------------------------
__device__ float g_q[(size_t)BB * HH * TT * DD];   // (b,h,t,d)
__device__ float g_k[(size_t)BB * HH * TT * DD];
__device__ float g_v[(size_t)BB * HH * TT * DD];
// bf16 hi/lo precision splits
__device__ __nv_bfloat16 g_xhi[(size_t)MM * CC];         // x        [M][K]
__device__ __nv_bfloat16 g_xlo[(size_t)MM * CC];
__device__ __nv_bfloat16 g_wahi[(size_t)3 * CC * CC];    // W_attn^T [N=3072][K=1024]
__device__ __nv_bfloat16 g_walo[(size_t)3 * CC * CC];
__device__ __nv_bfloat16 g_wphi[(size_t)CC * CC];        // W_proj^T [N=1024][K=1024]
__device__ __nv_bfloat16 g_wplo[(size_t)CC * CC];
__device__ __nv_bfloat16 g_ahi[(size_t)MM * CC];         // attention out [M][K]
__device__ __nv_bfloat16 g_alo[(size_t)MM * CC];

// ---------------------------------------------------------------------------
// PTX helpers (sm_80+ portable: cp.async / ldmatrix / mma.sync — no tcgen05)
// ---------------------------------------------------------------------------
__device__ __forceinline__ uint32_t smem_to_u32(const void* smem_ptr) {
    uint32_t addr;
    asm("{ .reg .u64 tmp; cvta.to.shared.u64 tmp, %1; cvt.u32.u64 %0, tmp; }"
        : "=r"(addr) : "l"(smem_ptr));
    return addr;
}

__device__ __forceinline__ void cpasync16(uint32_t s, const void* g) {
    asm volatile("cp.async.cg.shared.global [%0], [%1], 16;" :: "r"(s), "l"(g) : "memory");
}

#define CP_COMMIT()  asm volatile("cp.async.commit_group;" ::: "memory")
#define CP_WAIT(n)   asm volatile("cp.async.wait_group %0;" :: "n"(n) : "memory")

#define LDSM_X4(r, addr) \
    asm volatile("ldmatrix.sync.aligned.m8n8.x4.shared.b16 {%0,%1,%2,%3}, [%4];" \
        : "=r"((r)[0]), "=r"((r)[1]), "=r"((r)[2]), "=r"((r)[3]) : "r"(addr))

#define MMA_BF16(c, a, b0, b1) \
    asm volatile("mma.sync.aligned.m16n8k16.row.col.f32.bf16.bf16.f32 " \
        "{%0,%1,%2,%3}, {%4,%5,%6,%7}, {%8,%9}, {%0,%1,%2,%3};" \
        : "+f"((c)[0]), "+f"((c)[1]), "+f"((c)[2]), "+f"((c)[3]) \
        : "r"((a)[0]), "r"((a)[1]), "r"((a)[2]), "r"((a)[3]), "r"(b0), "r"(b1))

// ---------------------------------------------------------------------------
// Preprocessing: split fp32 -> (hi, lo) bf16
// ---------------------------------------------------------------------------
__device__ __forceinline__ void bf16_split(float v, __nv_bfloat16& h, __nv_bfloat16& l) {
    h = __float2bfloat16(v);
    l = __float2bfloat16(v - __bfloat162float(h));
}

__global__ __launch_bounds__(256) void split_x_kernel(const float* __restrict__ x) {
    size_t i = (size_t)blockIdx.x * 256 + threadIdx.x;  // over MM*CC/4 float4s
    float4 v = ((const float4*)x)[i];
    __nv_bfloat16 h0, h1, h2, h3, l0, l1, l2, l3;
    bf16_split(v.x, h0, l0); bf16_split(v.y, h1, l1);
    bf16_split(v.z, h2, l2); bf16_split(v.w, h3, l3);
    __nv_bfloat162* ph = (__nv_bfloat162*)(g_xhi + i * 4);
    __nv_bfloat162* pl = (__nv_bfloat162*)(g_xlo + i * 4);
    ph[0] = __nv_bfloat162{h0, h1}; ph[1] = __nv_bfloat162{h2, h3};
    pl[0] = __nv_bfloat162{l0, l1}; pl[1] = __nv_bfloat162{l2, l3};
}

// Transpose + split: W [K=1024][NN] fp32 -> Wt_hi/lo [NN][1024] bf16
template <int NN, int WHICH>
__global__ __launch_bounds__(256) void tsplit_w_kernel(const float* __restrict__ W) {
    __shared__ float tile[32][33];
    __nv_bfloat16* Whi = (WHICH == 0) ? g_wahi : g_wphi;
    __nv_bfloat16* Wlo = (WHICH == 0) ? g_walo : g_wplo;
    const int nb = blockIdx.x * 32;
    const int kb = blockIdx.y * 32;
    const int tx = threadIdx.x, ty = threadIdx.y;
#pragma unroll
    for (int r = 0; r < 4; ++r)
        tile[ty + r * 8][tx] = W[(size_t)(kb + ty + r * 8) * NN + nb + tx];
    __syncthreads();
#pragma unroll
    for (int r = 0; r < 4; ++r) {
        const int n = nb + ty + r * 8;
        const int k = kb + tx;
        float v = tile[tx][ty + r * 8];
        __nv_bfloat16 h, l;
        bf16_split(v, h, l);
        Whi[(size_t)n * 1024 + k] = h;
        Wlo[(size_t)n * 1024 + k] = l;
    }
}

// ---------------------------------------------------------------------------
// bf16x3 tensor-core GEMM (mma.sync.m16n8k16): C = A[M,K] @ Wt[N,K]^T + bias
// CTA tile 128x128, K-chunk 64 bf16 (128B rows, SW128 xor swizzle).
// 8 warps as 2(m) x 4(n); warp tile 64x32 = 4 m-frags x 4 n-frags.
// Double-buffered SMEM (2 x 64KB) fed by cp.async pipelining.
// 3 MMAs per accumulator per k16-step: Ahi*Bhi + Ahi*Blo + Alo*Bhi.
// MODE 0: A = x split, scatter into g_q/g_k/g_v.  MODE 1: A = att split -> Out.
// ---------------------------------------------------------------------------
template <int Ndim, int MODE>
__global__ __launch_bounds__(256) void hmma_gemm_kernel(
    const float* __restrict__ bias, float* __restrict__ Out)
{
    extern __shared__ __align__(1024) char smem[];
    // buffer b at b*65536: Ahi@0, Alo@16384, Bhi@32768, Blo@49152 (16KB each)
    const uint32_t sbase = smem_to_u32(smem);
    const int tid = threadIdx.x;
    const int lane = tid & 31;
    const int wid = tid >> 5;
    const int wm = wid >> 2;   // 0..1
    const int wn = wid & 3;    // 0..3
    const int m0 = blockIdx.y * 128;
    const int n0 = blockIdx.x * 128;
    constexpr int KT = 16;     // 1024 / 64

    const __nv_bfloat16* Ahi = (MODE == 0) ? g_xhi : g_ahi;
    const __nv_bfloat16* Alo = (MODE == 0) ? g_xlo : g_alo;
    const __nv_bfloat16* Bhi = (MODE == 0) ? g_wahi : g_wphi;
    const __nv_bfloat16* Blo = (MODE == 0) ? g_walo : g_wplo;

    const char* gAh = (const char*)Ahi + (size_t)m0 * 2048;  // row stride 1024 bf16
    const char* gAl = (const char*)Alo + (size_t)m0 * 2048;
    const char* gBh = (const char*)Bhi + (size_t)n0 * 2048;
    const char* gBl = (const char*)Blo + (size_t)n0 * 2048;

    float acc[4][4][4];
#pragma unroll
    for (int mf = 0; mf < 4; ++mf)
#pragma unroll
        for (int nf = 0; nf < 4; ++nf)
#pragma unroll
            for (int e = 0; e < 4; ++e) acc[mf][nf][e] = 0.f;

    // per-thread global->smem mapping (4 chunks of 16B per plane)
    // idx = tid + i*256 -> row = idx>>3, ch = idx&7; swizzled 16B slot = ch ^ (row&7)
    auto issue = [&](int c) {
        const uint32_t tb = sbase + (uint32_t)(c & 1) * 65536;
        const int kb = c * 128;  // bytes along K
#pragma unroll
        for (int i = 0; i < 4; ++i) {
            const int idx = tid + i * 256;
            const int row = idx >> 3;
            const int ch = idx & 7;
            const uint32_t soff = row * 128 + ((ch ^ (row & 7)) << 4);
            const size_t goff = (size_t)row * 2048 + ch * 16 + kb;
            cpasync16(tb + 0     + soff, gAh + goff);
            cpasync16(tb + 16384 + soff, gAl + goff);
            cpasync16(tb + 32768 + soff, gBh + goff);
            cpasync16(tb + 49152 + soff, gBl + goff);
        }
        CP_COMMIT();
    };

    issue(0);

    const int q = lane >> 3;          // ldmatrix quad (matrix id)
    const int iq = lane & 7;          // row within matrix
    const int rowoff_a = ((q & 1) << 3) + iq;  // 0..15
    const int khalf = q >> 1;                  // 0 or 1 (16B chunk within kstep)

    for (int c = 0; c < KT; ++c) {
        if (c + 1 < KT) { issue(c + 1); CP_WAIT(1); }
        else           { CP_WAIT(0); }
        __syncthreads();

        const uint32_t tb = sbase + (uint32_t)(c & 1) * 65536;
        const uint32_t aT = tb, alT = tb + 16384, bT = tb + 32768, blT = tb + 49152;

#pragma unroll
        for (int ks = 0; ks < 4; ++ks) {
            const int cch = ks * 2 + khalf;   // 16B chunk index along K
            uint32_t ah[4][4], al[4][4];
#pragma unroll
            for (int mf = 0; mf < 4; ++mf) {
                const int row = wm * 64 + mf * 16 + rowoff_a;
                const uint32_t off = row * 128 + ((cch ^ (row & 7)) << 4);
                LDSM_X4(ah[mf], aT + off);
                LDSM_X4(al[mf], alT + off);
            }
            uint32_t bh[4][2], bl[4][2];
#pragma unroll
            for (int np = 0; np < 2; ++np) {
                const int row = wn * 32 + np * 16 + rowoff_a;
                const uint32_t off = row * 128 + ((cch ^ (row & 7)) << 4);
                uint32_t r[4];
                LDSM_X4(r, bT + off);
                bh[2 * np][0] = r[0]; bh[2 * np][1] = r[2];
                bh[2 * np + 1][0] = r[1]; bh[2 * np + 1][1] = r[3];
                LDSM_X4(r, blT + off);
                bl[2 * np][0] = r[0]; bl[2 * np][1] = r[2];
                bl[2 * np + 1][0] = r[1]; bl[2 * np + 1][1] = r[3];
            }
            // combo-outer ordering: same accumulator reused every 16 MMAs
#pragma unroll
            for (int mf = 0; mf < 4; ++mf)
#pragma unroll
                for (int nf = 0; nf < 4; ++nf)
                    MMA_BF16(acc[mf][nf], ah[mf], bh[nf][0], bh[nf][1]);
#pragma unroll
            for (int mf = 0; mf < 4; ++mf)
#pragma unroll
                for (int nf = 0; nf < 4; ++nf)
                    MMA_BF16(acc[mf][nf], ah[mf], bl[nf][0], bl[nf][1]);
#pragma unroll
            for (int mf = 0; mf < 4; ++mf)
#pragma unroll
                for (int nf = 0; nf < 4; ++nf)
                    MMA_BF16(acc[mf][nf], al[mf], bh[nf][0], bh[nf][1]);
        }
        __syncthreads();  // protect buffer (c&1) before issue(c+2) overwrites it
    }

    // Epilogue. Fragment element map: c0,c1 -> (row g, col 2t,2t+1); c2,c3 -> row g+8.
    const int g = lane >> 2, t = lane & 3;
#pragma unroll
    for (int mf = 0; mf < 4; ++mf) {
        const int r_lo = m0 + wm * 64 + mf * 16 + g;
#pragma unroll
        for (int nf = 0; nf < 4; ++nf) {
            const int col = n0 + wn * 32 + nf * 8 + 2 * t;
            const float b0 = bias[col], b1 = bias[col + 1];
            float2 v0 = {acc[mf][nf][0] + b0, acc[mf][nf][1] + b1};
            float2 v1 = {acc[mf][nf][2] + b0, acc[mf][nf][3] + b1};
            if (MODE == 0) {
                const int which = col >> 10;
                const int ci = col & 1023;
                const int hh = ci >> 6;
                const int dd = ci & 63;
                float* dst = (which == 0) ? g_q : ((which == 1) ? g_k : g_v);
                const int b_lo = r_lo >> 11, t_lo = r_lo & 2047;
                *(float2*)(dst + (((size_t)b_lo * HH + hh) * TT + t_lo) * DD + dd) = v0;
                const int r_hi = r_lo + 8;
                const int b_hi = r_hi >> 11, t_hi = r_hi & 2047;
                *(float2*)(dst + (((size_t)b_hi * HH + hh) * TT + t_hi) * DD + dd) = v1;
            } else {
                *(float2*)(Out + (size_t)r_lo * Ndim + col) = v0;
                *(float2*)(Out + (size_t)(r_lo + 8) * Ndim + col) = v1;
            }
        }
    }
}

// ---------------------------------------------------------------------------
// Flash-style causal attention with ALiBi + temperature (fp32, unchanged
// math from the passing R4 kernel). Epilogue writes bf16 hi/lo splits of the
// attention output as the A operand of the proj GEMM.
// ---------------------------------------------------------------------------
__global__ __launch_bounds__(64) void attn_kernel(const float* __restrict__ temp)
{
    __shared__ __align__(16) float Ksh[64 * 64];
    __shared__ __align__(16) float Vsh[64 * 64];
    __shared__ float Ssh[64 * 64];

    const int bh = blockIdx.y;
    const int qt = blockIdx.x;
    const int b = bh >> 4;
    const int h = bh & 15;
    const int tid = threadIdx.x;
    const int qrow = qt * 64 + tid;

    const float LOG2E = 1.44269504088896340736f;
    const float invt = 1.0f / temp[0];
    const float qscale = 0.125f * invt * LOG2E;
    const float slope = exp2f(-0.5f * (float)(h + 1)) * LOG2E;

    float qr[64];
    {
        const float4* qp = (const float4*)(g_q + ((size_t)bh * TT + qrow) * DD);
#pragma unroll
        for (int i = 0; i < 16; ++i) {
            float4 f = qp[i];
            qr[4 * i + 0] = f.x * qscale;
            qr[4 * i + 1] = f.y * qscale;
            qr[4 * i + 2] = f.z * qscale;
            qr[4 * i + 3] = f.w * qscale;
        }
    }

    float o[64];
#pragma unroll
    for (int i = 0; i < 64; ++i) o[i] = 0.f;
    float m = -1e30f;
    float l = 0.f;

    float4* K4 = (float4*)Ksh;
    float4* V4 = (float4*)Vsh;

    for (int kt = 0; kt <= qt; ++kt) {
        const float4* kp = (const float4*)(g_k + ((size_t)bh * TT + kt * 64) * DD);
        const float4* vp = (const float4*)(g_v + ((size_t)bh * TT + kt * 64) * DD);
        __syncthreads();
#pragma unroll
        for (int i = 0; i < 16; ++i) {
            K4[i * 64 + tid] = kp[i * 64 + tid];
            V4[i * 64 + tid] = vp[i * 64 + tid];
        }
        __syncthreads();

        const float base = (float)(kt * 64 - qrow);
        const bool diag = (kt == qt);
        float tmax = -1e30f;

#pragma unroll 2
        for (int j = 0; j < 64; ++j) {
            const float4* kj = K4 + j * 16;
            float a0 = 0.f, a1 = 0.f, a2 = 0.f, a3 = 0.f;
#pragma unroll
            for (int kk = 0; kk < 16; ++kk) {
                float4 kv = kj[kk];
                a0 += qr[4 * kk + 0] * kv.x;
                a1 += qr[4 * kk + 1] * kv.y;
                a2 += qr[4 * kk + 2] * kv.z;
                a3 += qr[4 * kk + 3] * kv.w;
            }
            float sv = (a0 + a1) + (a2 + a3) + slope * (base + (float)j);
            if (diag && j > tid) sv = -1e30f;
            Ssh[j * 64 + tid] = sv;
            tmax = fmaxf(tmax, sv);
        }

        const float mnew = fmaxf(m, tmax);
        const float alpha = exp2f(m - mnew);
        m = mnew;
        l *= alpha;
#pragma unroll
        for (int d = 0; d < 64; ++d) o[d] *= alpha;

#pragma unroll 2
        for (int j = 0; j < 64; ++j) {
            const float p = exp2f(Ssh[j * 64 + tid] - m);
            l += p;
            const float4* vj = V4 + j * 16;
#pragma unroll
            for (int dd = 0; dd < 16; ++dd) {
                float4 vv = vj[dd];
                o[4 * dd + 0] += p * vv.x;
                o[4 * dd + 1] += p * vv.y;
                o[4 * dd + 2] += p * vv.z;
                o[4 * dd + 3] += p * vv.w;
            }
        }
    }

    const float inv_l = 1.0f / l;
    const size_t rowoff = (size_t)(b * TT + qrow) * CC + h * DD;
    __nv_bfloat16* ahp = g_ahi + rowoff;
    __nv_bfloat16* alp = g_alo + rowoff;
#pragma unroll
    for (int i = 0; i < 64; i += 2) {
        float v0 = o[i] * inv_l;
        float v1 = o[i + 1] * inv_l;
        __nv_bfloat16 h0, h1, l0, l1;
        bf16_split(v0, h0, l0);
        bf16_split(v1, h1, l1);
        *(__nv_bfloat162*)(ahp + i) = __nv_bfloat162{h0, h1};
        *(__nv_bfloat162*)(alp + i) = __nv_bfloat162{l0, l1};
    }
}

// ---------------------------------------------------------------------------
// Harness entry
// ---------------------------------------------------------------------------
extern "C" void kernel_launch(void* const* d_in, const int* in_sizes, int n_in,
                              void* d_out, int out_size)
{
    const float* x      = (const float*)d_in[0];
    const float* W_attn = (const float*)d_in[1];
    const float* b_attn = (const float*)d_in[2];
    const float* W_proj = (const float*)d_in[3];
    const float* b_proj = (const float*)d_in[4];
    const float* temp   = (const float*)d_in[5];
    float* out = (float*)d_out;

    const int SMEM_BYTES = 2 * 65536;  // 131072
    cudaFuncSetAttribute(hmma_gemm_kernel<3 * CC, 0>,
                         cudaFuncAttributeMaxDynamicSharedMemorySize, SMEM_BYTES);
    cudaFuncSetAttribute(hmma_gemm_kernel<CC, 1>,
                         cudaFuncAttributeMaxDynamicSharedMemorySize, SMEM_BYTES);

    // 0) precision-split inputs (bf16 hi/lo) + weight transposes
    split_x_kernel<<<(MM * CC / 4) / 256, 256>>>(x);
    tsplit_w_kernel<3 * CC, 0><<<dim3(3 * CC / 32, CC / 32), dim3(32, 8)>>>(W_attn);
    tsplit_w_kernel<CC, 1><<<dim3(CC / 32, CC / 32), dim3(32, 8)>>>(W_proj);

    // 1) QKV = x @ W_attn + b_attn  (bf16x3 HMMA, scatter to q/k/v)
    hmma_gemm_kernel<3 * CC, 0><<<dim3(3 * CC / 128, MM / 128), 256, SMEM_BYTES>>>(
        b_attn, nullptr);

    // 2) causal ALiBi attention (fp32) -> bf16-split A for proj
    attn_kernel<<<dim3(TT / 64, BB * HH), 64>>>(temp);

    // 3) out = att @ W_proj + b_proj  (bf16x3 HMMA)
    hmma_gemm_kernel<CC, 1><<<dim3(CC / 128, MM / 128), 256, SMEM_BYTES>>>(
        b_proj, out);
}

// round 8
// speedup vs baseline: 2.6534x; 2.0233x over previous
#include <cuda_runtime.h>
#include <cuda_bf16.h>
#include <cstdint>

// Problem constants
#define BB 2
#define TT 2048
#define CC 1024
#define HH 16
#define DD 64
#define MM (BB * TT)   // 4096 rows

// ---------------------------------------------------------------------------
// Device scratch (allocation-free per harness rules)
// ---------------------------------------------------------------------------
// q/k/v in bf16 hi/lo split, layout (b,h,t,d), d contiguous (128B rows)
__device__ __nv_bfloat16 g_qhi[(size_t)BB * HH * TT * DD];
__device__ __nv_bfloat16 g_qlo[(size_t)BB * HH * TT * DD];
__device__ __nv_bfloat16 g_khi[(size_t)BB * HH * TT * DD];
__device__ __nv_bfloat16 g_klo[(size_t)BB * HH * TT * DD];
__device__ __nv_bfloat16 g_vhi[(size_t)BB * HH * TT * DD];
__device__ __nv_bfloat16 g_vlo[(size_t)BB * HH * TT * DD];
// bf16 hi/lo precision splits for GEMM operands
__device__ __nv_bfloat16 g_xhi[(size_t)MM * CC];         // x        [M][K]
__device__ __nv_bfloat16 g_xlo[(size_t)MM * CC];
__device__ __nv_bfloat16 g_wahi[(size_t)3 * CC * CC];    // W_attn^T [N=3072][K=1024]
__device__ __nv_bfloat16 g_walo[(size_t)3 * CC * CC];
__device__ __nv_bfloat16 g_wphi[(size_t)CC * CC];        // W_proj^T [N=1024][K=1024]
__device__ __nv_bfloat16 g_wplo[(size_t)CC * CC];
__device__ __nv_bfloat16 g_ahi[(size_t)MM * CC];         // attention out [M][K]
__device__ __nv_bfloat16 g_alo[(size_t)MM * CC];

// ---------------------------------------------------------------------------
// PTX helpers (sm_80+ portable: cp.async / ldmatrix / mma.sync)
// ---------------------------------------------------------------------------
__device__ __forceinline__ uint32_t smem_to_u32(const void* smem_ptr) {
    uint32_t addr;
    asm("{ .reg .u64 tmp; cvta.to.shared.u64 tmp, %1; cvt.u32.u64 %0, tmp; }"
        : "=r"(addr) : "l"(smem_ptr));
    return addr;
}

__device__ __forceinline__ void cpasync16(uint32_t s, const void* g) {
    asm volatile("cp.async.cg.shared.global [%0], [%1], 16;" :: "r"(s), "l"(g) : "memory");
}

#define CP_COMMIT()  asm volatile("cp.async.commit_group;" ::: "memory")
#define CP_WAIT(n)   asm volatile("cp.async.wait_group %0;" :: "n"(n) : "memory")

#define LDSM_X4(r, addr) \
    asm volatile("ldmatrix.sync.aligned.m8n8.x4.shared.b16 {%0,%1,%2,%3}, [%4];" \
        : "=r"((r)[0]), "=r"((r)[1]), "=r"((r)[2]), "=r"((r)[3]) : "r"(addr))

#define LDSM_X4_T(r, addr) \
    asm volatile("ldmatrix.sync.aligned.m8n8.x4.trans.shared.b16 {%0,%1,%2,%3}, [%4];" \
        : "=r"((r)[0]), "=r"((r)[1]), "=r"((r)[2]), "=r"((r)[3]) : "r"(addr))

#define MMA_BF16(c, a, b0, b1) \
    asm volatile("mma.sync.aligned.m16n8k16.row.col.f32.bf16.bf16.f32 " \
        "{%0,%1,%2,%3}, {%4,%5,%6,%7}, {%8,%9}, {%0,%1,%2,%3};" \
        : "+f"((c)[0]), "+f"((c)[1]), "+f"((c)[2]), "+f"((c)[3]) \
        : "r"((a)[0]), "r"((a)[1]), "r"((a)[2]), "r"((a)[3]), "r"(b0), "r"(b1))

// fast exp2 on the FMA pipe (no MUFU). x clamped to >= -126; |err| < ~1e-7.
__device__ __forceinline__ float fexp2(float x) {
    x = fmaxf(x, -126.0f);
    float t = x + 12582912.0f;        // 1.5*2^23: RN rounds x to nearest int
    float r = t - 12582912.0f;
    float f = x - r;                  // f in [-0.5, 0.5]
    int e = (__float_as_int(t) + (127 - 0x400000)) << 23;  // 2^round(x) bits
    float p = 1.5353361883e-4f;
    p = fmaf(p, f, 1.3398874403e-3f);
    p = fmaf(p, f, 9.6184373577e-3f);
    p = fmaf(p, f, 5.5503324712e-2f);
    p = fmaf(p, f, 2.4022647914e-1f);
    p = fmaf(p, f, 6.9314720286e-1f);
    p = fmaf(p, f, 1.0f);
    return p * __int_as_float(e);
}

// ---------------------------------------------------------------------------
// Preprocessing: split fp32 -> (hi, lo) bf16
// ---------------------------------------------------------------------------
__device__ __forceinline__ void bf16_split(float v, __nv_bfloat16& h, __nv_bfloat16& l) {
    h = __float2bfloat16(v);
    l = __float2bfloat16(v - __bfloat162float(h));
}

__device__ __forceinline__ uint32_t pack2bf(float x, float y) {
    __nv_bfloat162 v{__float2bfloat16(x), __float2bfloat16(y)};
    return *(uint32_t*)&v;
}

__global__ __launch_bounds__(256) void split_x_kernel(const float* __restrict__ x) {
    size_t i = (size_t)blockIdx.x * 256 + threadIdx.x;  // over MM*CC/4 float4s
    float4 v = ((const float4*)x)[i];
    __nv_bfloat16 h0, h1, h2, h3, l0, l1, l2, l3;
    bf16_split(v.x, h0, l0); bf16_split(v.y, h1, l1);
    bf16_split(v.z, h2, l2); bf16_split(v.w, h3, l3);
    __nv_bfloat162* ph = (__nv_bfloat162*)(g_xhi + i * 4);
    __nv_bfloat162* pl = (__nv_bfloat162*)(g_xlo + i * 4);
    ph[0] = __nv_bfloat162{h0, h1}; ph[1] = __nv_bfloat162{h2, h3};
    pl[0] = __nv_bfloat162{l0, l1}; pl[1] = __nv_bfloat162{l2, l3};
}

// Transpose + split: W [K=1024][NN] fp32 -> Wt_hi/lo [NN][1024] bf16
template <int NN, int WHICH>
__global__ __launch_bounds__(256) void tsplit_w_kernel(const float* __restrict__ W) {
    __shared__ float tile[32][33];
    __nv_bfloat16* Whi = (WHICH == 0) ? g_wahi : g_wphi;
    __nv_bfloat16* Wlo = (WHICH == 0) ? g_walo : g_wplo;
    const int nb = blockIdx.x * 32;
    const int kb = blockIdx.y * 32;
    const int tx = threadIdx.x, ty = threadIdx.y;
#pragma unroll
    for (int r = 0; r < 4; ++r)
        tile[ty + r * 8][tx] = W[(size_t)(kb + ty + r * 8) * NN + nb + tx];
    __syncthreads();
#pragma unroll
    for (int r = 0; r < 4; ++r) {
        const int n = nb + ty + r * 8;
        const int k = kb + tx;
        float v = tile[tx][ty + r * 8];
        __nv_bfloat16 h, l;
        bf16_split(v, h, l);
        Whi[(size_t)n * 1024 + k] = h;
        Wlo[(size_t)n * 1024 + k] = l;
    }
}

// ---------------------------------------------------------------------------
// bf16x3 tensor-core GEMM (mma.sync.m16n8k16): C = A[M,K] @ Wt[N,K]^T + bias
// CTA tile 128x128, K-chunk 64 bf16 (128B rows, SW128 xor swizzle).
// 8 warps as 2(m) x 4(n); warp tile 64x32 = 4 m-frags x 4 n-frags.
// MODE 0: A = x split, scatter into q/k/v bf16 hi/lo.  MODE 1: att -> Out.
// ---------------------------------------------------------------------------
template <int Ndim, int MODE>
__global__ __launch_bounds__(256) void hmma_gemm_kernel(
    const float* __restrict__ bias, float* __restrict__ Out)
{
    extern __shared__ __align__(1024) char smem[];
    const uint32_t sbase = smem_to_u32(smem);
    const int tid = threadIdx.x;
    const int lane = tid & 31;
    const int wid = tid >> 5;
    const int wm = wid >> 2;   // 0..1
    const int wn = wid & 3;    // 0..3
    const int m0 = blockIdx.y * 128;
    const int n0 = blockIdx.x * 128;
    constexpr int KT = 16;     // 1024 / 64

    const __nv_bfloat16* Ahi = (MODE == 0) ? g_xhi : g_ahi;
    const __nv_bfloat16* Alo = (MODE == 0) ? g_xlo : g_alo;
    const __nv_bfloat16* Bhi = (MODE == 0) ? g_wahi : g_wphi;
    const __nv_bfloat16* Blo = (MODE == 0) ? g_walo : g_wplo;

    const char* gAh = (const char*)Ahi + (size_t)m0 * 2048;
    const char* gAl = (const char*)Alo + (size_t)m0 * 2048;
    const char* gBh = (const char*)Bhi + (size_t)n0 * 2048;
    const char* gBl = (const char*)Blo + (size_t)n0 * 2048;

    float acc[4][4][4];
#pragma unroll
    for (int mf = 0; mf < 4; ++mf)
#pragma unroll
        for (int nf = 0; nf < 4; ++nf)
#pragma unroll
            for (int e = 0; e < 4; ++e) acc[mf][nf][e] = 0.f;

    auto issue = [&](int c) {
        const uint32_t tb = sbase + (uint32_t)(c & 1) * 65536;
        const int kb = c * 128;
#pragma unroll
        for (int i = 0; i < 4; ++i) {
            const int idx = tid + i * 256;
            const int row = idx >> 3;
            const int ch = idx & 7;
            const uint32_t soff = row * 128 + ((ch ^ (row & 7)) << 4);
            const size_t goff = (size_t)row * 2048 + ch * 16 + kb;
            cpasync16(tb + 0     + soff, gAh + goff);
            cpasync16(tb + 16384 + soff, gAl + goff);
            cpasync16(tb + 32768 + soff, gBh + goff);
            cpasync16(tb + 49152 + soff, gBl + goff);
        }
        CP_COMMIT();
    };

    issue(0);

    const int q = lane >> 3;
    const int iq = lane & 7;
    const int rowoff_a = ((q & 1) << 3) + iq;
    const int khalf = q >> 1;

    for (int c = 0; c < KT; ++c) {
        if (c + 1 < KT) { issue(c + 1); CP_WAIT(1); }
        else           { CP_WAIT(0); }
        __syncthreads();

        const uint32_t tb = sbase + (uint32_t)(c & 1) * 65536;
        const uint32_t aT = tb, alT = tb + 16384, bT = tb + 32768, blT = tb + 49152;

#pragma unroll
        for (int ks = 0; ks < 4; ++ks) {
            const int cch = ks * 2 + khalf;
            uint32_t ah[4][4], al[4][4];
#pragma unroll
            for (int mf = 0; mf < 4; ++mf) {
                const int row = wm * 64 + mf * 16 + rowoff_a;
                const uint32_t off = row * 128 + ((cch ^ (row & 7)) << 4);
                LDSM_X4(ah[mf], aT + off);
                LDSM_X4(al[mf], alT + off);
            }
            uint32_t bh[4][2], bl[4][2];
#pragma unroll
            for (int np = 0; np < 2; ++np) {
                const int row = wn * 32 + np * 16 + rowoff_a;
                const uint32_t off = row * 128 + ((cch ^ (row & 7)) << 4);
                uint32_t r[4];
                LDSM_X4(r, bT + off);
                bh[2 * np][0] = r[0]; bh[2 * np][1] = r[2];
                bh[2 * np + 1][0] = r[1]; bh[2 * np + 1][1] = r[3];
                LDSM_X4(r, blT + off);
                bl[2 * np][0] = r[0]; bl[2 * np][1] = r[2];
                bl[2 * np + 1][0] = r[1]; bl[2 * np + 1][1] = r[3];
            }
#pragma unroll
            for (int mf = 0; mf < 4; ++mf)
#pragma unroll
                for (int nf = 0; nf < 4; ++nf)
                    MMA_BF16(acc[mf][nf], ah[mf], bh[nf][0], bh[nf][1]);
#pragma unroll
            for (int mf = 0; mf < 4; ++mf)
#pragma unroll
                for (int nf = 0; nf < 4; ++nf)
                    MMA_BF16(acc[mf][nf], ah[mf], bl[nf][0], bl[nf][1]);
#pragma unroll
            for (int mf = 0; mf < 4; ++mf)
#pragma unroll
                for (int nf = 0; nf < 4; ++nf)
                    MMA_BF16(acc[mf][nf], al[mf], bh[nf][0], bh[nf][1]);
        }
        __syncthreads();
    }

    // Epilogue. Frag map: c0,c1 -> (row g, cols 2t,2t+1); c2,c3 -> row g+8.
    const int g = lane >> 2, t = lane & 3;
#pragma unroll
    for (int mf = 0; mf < 4; ++mf) {
        const int r_lo = m0 + wm * 64 + mf * 16 + g;
#pragma unroll
        for (int nf = 0; nf < 4; ++nf) {
            const int col = n0 + wn * 32 + nf * 8 + 2 * t;
            const float b0 = bias[col], b1 = bias[col + 1];
            float v00 = acc[mf][nf][0] + b0, v01 = acc[mf][nf][1] + b1;
            float v10 = acc[mf][nf][2] + b0, v11 = acc[mf][nf][3] + b1;
            if (MODE == 0) {
                // split into bf16 hi/lo and scatter to q/k/v (b,h,t,d)
                const int which = col >> 10;
                const int ci = col & 1023;
                const int hh = ci >> 6;
                const int dd = ci & 63;
                __nv_bfloat16* dh = (which == 0) ? g_qhi : ((which == 1) ? g_khi : g_vhi);
                __nv_bfloat16* dl = (which == 0) ? g_qlo : ((which == 1) ? g_klo : g_vlo);
                __nv_bfloat16 h0, h1, l0, l1;
                const int b_lo = r_lo >> 11, t_lo = r_lo & 2047;
                size_t off = (((size_t)b_lo * HH + hh) * TT + t_lo) * DD + dd;
                bf16_split(v00, h0, l0); bf16_split(v01, h1, l1);
                *(__nv_bfloat162*)(dh + off) = __nv_bfloat162{h0, h1};
                *(__nv_bfloat162*)(dl + off) = __nv_bfloat162{l0, l1};
                const int r_hi = r_lo + 8;
                const int b_hi = r_hi >> 11, t_hi = r_hi & 2047;
                off = (((size_t)b_hi * HH + hh) * TT + t_hi) * DD + dd;
                bf16_split(v10, h0, l0); bf16_split(v11, h1, l1);
                *(__nv_bfloat162*)(dh + off) = __nv_bfloat162{h0, h1};
                *(__nv_bfloat162*)(dl + off) = __nv_bfloat162{l0, l1};
            } else {
                *(float2*)(Out + (size_t)r_lo * Ndim + col) = float2{v00, v01};
                *(float2*)(Out + (size_t)(r_lo + 8) * Ndim + col) = float2{v10, v11};
            }
        }
    }
}

// ---------------------------------------------------------------------------
// Tensor-core flash attention with ALiBi + temperature.
// CTA: 128 q-rows of one (b,h). 8 warps x m16. K/V tiles of 64 keys,
// double-buffered cp.async. bf16x3 on QK^T and P*V. exp2 via FMA polynomial.
// SMEM: Q stage 32KB @0 (hi 16K, lo 16K); buffers @32768 + buf*32768:
//       Khi@0 Klo@8192 Vhi@16384 Vlo@24576 (8KB each: 64 rows x 128B).
// ---------------------------------------------------------------------------
__global__ __launch_bounds__(256) void attn_mma_kernel(const float* __restrict__ temp)
{
    extern __shared__ __align__(1024) char smem[];
    const uint32_t sb = smem_to_u32(smem);
    const int tid = threadIdx.x;
    const int lane = tid & 31;
    const int wid = tid >> 5;
    const int bh = blockIdx.y;
    const int qt = (int)gridDim.x - 1 - blockIdx.x;   // heavy tiles first
    const int b = bh >> 4;
    const int h = bh & 15;

    const float LOG2E = 1.44269504088896340736f;
    const float qscale = 0.125f * (1.0f / temp[0]) * LOG2E;
    const float slope = exp2f(-0.5f * (float)(h + 1)) * LOG2E;

    const int q8 = lane >> 3;
    const int iq = lane & 7;
    const int rowoff = ((q8 & 1) << 3) + iq;   // 0..15
    const int khalf = q8 >> 1;                 // 0/1
    const int g = lane >> 2, t = lane & 3;

    const char* gQh = (const char*)g_qhi + ((size_t)bh * TT + qt * 128) * 128;
    const char* gQl = (const char*)g_qlo + ((size_t)bh * TT + qt * 128) * 128;
    const char* gKh = (const char*)g_khi + (size_t)bh * TT * 128;
    const char* gKl = (const char*)g_klo + (size_t)bh * TT * 128;
    const char* gVh = (const char*)g_vhi + (size_t)bh * TT * 128;
    const char* gVl = (const char*)g_vlo + (size_t)bh * TT * 128;

    const int nkt = 2 * qt + 2;  // number of 64-key tiles (causal)

    // ---- stage Q (group 0) ----
#pragma unroll
    for (int i = 0; i < 4; ++i) {
        const int idx = tid + i * 256;
        const int row = idx >> 3;
        const int ch = idx & 7;
        const uint32_t soff = row * 128 + ((ch ^ (row & 7)) << 4);
        const size_t goff = (size_t)row * 128 + ch * 16;
        cpasync16(sb + 0     + soff, gQh + goff);
        cpasync16(sb + 16384 + soff, gQl + goff);
    }
    CP_COMMIT();

    auto issue_kv = [&](int kt) {
        const uint32_t tb = sb + 32768 + (uint32_t)(kt & 1) * 32768;
        const size_t kbase = (size_t)kt * 64 * 128;
#pragma unroll
        for (int i = 0; i < 2; ++i) {
            const int idx = tid + i * 256;
            const int row = idx >> 3;
            const int ch = idx & 7;
            const uint32_t soff = row * 128 + ((ch ^ (row & 7)) << 4);
            const size_t goff = kbase + (size_t)row * 128 + ch * 16;
            cpasync16(tb + 0     + soff, gKh + goff);
            cpasync16(tb + 8192  + soff, gKl + goff);
            cpasync16(tb + 16384 + soff, gVh + goff);
            cpasync16(tb + 24576 + soff, gVl + goff);
        }
        CP_COMMIT();
    };

    issue_kv(0);
    CP_WAIT(1);          // Q complete (kv0 may be in flight)
    __syncthreads();

    // ---- Q fragments (resident) ----
    uint32_t qh[4][4], ql[4][4];
#pragma unroll
    for (int ks = 0; ks < 4; ++ks) {
        const int row = wid * 16 + rowoff;
        const int cch = ks * 2 + khalf;
        const uint32_t off = row * 128 + ((cch ^ (row & 7)) << 4);
        LDSM_X4(qh[ks], sb + off);
        LDSM_X4(ql[ks], sb + 16384 + off);
    }

    float oacc[8][4];
#pragma unroll
    for (int nd = 0; nd < 8; ++nd)
#pragma unroll
        for (int e = 0; e < 4; ++e) oacc[nd][e] = 0.f;
    float m0 = -1e30f, m1 = -1e30f, l0 = 0.f, l1 = 0.f;

    const int qrow0 = qt * 128 + wid * 16 + g;
    const int qrow1 = qrow0 + 8;

    for (int kt = 0; kt < nkt; ++kt) {
        if (kt + 1 < nkt) { issue_kv(kt + 1); CP_WAIT(1); }
        else              { CP_WAIT(0); }
        __syncthreads();

        const uint32_t tb = sb + 32768 + (uint32_t)(kt & 1) * 32768;

        // ---- S = Q K^T (bf16x3) ----
        float sacc[8][4];
#pragma unroll
        for (int nf = 0; nf < 8; ++nf)
#pragma unroll
            for (int e = 0; e < 4; ++e) sacc[nf][e] = 0.f;

#pragma unroll
        for (int ks = 0; ks < 4; ++ks) {
            const int cch = ks * 2 + khalf;
            uint32_t kbh[8][2], kbl[8][2];
#pragma unroll
            for (int np = 0; np < 4; ++np) {
                const int row = np * 16 + rowoff;
                const uint32_t off = row * 128 + ((cch ^ (row & 7)) << 4);
                uint32_t r[4];
                LDSM_X4(r, tb + off);
                kbh[2 * np][0] = r[0]; kbh[2 * np][1] = r[2];
                kbh[2 * np + 1][0] = r[1]; kbh[2 * np + 1][1] = r[3];
                LDSM_X4(r, tb + 8192 + off);
                kbl[2 * np][0] = r[0]; kbl[2 * np][1] = r[2];
                kbl[2 * np + 1][0] = r[1]; kbl[2 * np + 1][1] = r[3];
            }
#pragma unroll
            for (int nf = 0; nf < 8; ++nf)
                MMA_BF16(sacc[nf], qh[ks], kbh[nf][0], kbh[nf][1]);
#pragma unroll
            for (int nf = 0; nf < 8; ++nf)
                MMA_BF16(sacc[nf], qh[ks], kbl[nf][0], kbl[nf][1]);
#pragma unroll
            for (int nf = 0; nf < 8; ++nf)
                MMA_BF16(sacc[nf], ql[ks], kbh[nf][0], kbh[nf][1]);
        }

        // ---- softmax (online) ----
        const bool maskt = (kt >= 2 * qt);
        float mx0 = -1e30f, mx1 = -1e30f;
#pragma unroll
        for (int nf = 0; nf < 8; ++nf) {
            const int key = kt * 64 + nf * 8 + 2 * t;
            float s0 = fmaf(sacc[nf][0], qscale, slope * (float)(key - qrow0));
            float s1 = fmaf(sacc[nf][1], qscale, slope * (float)(key + 1 - qrow0));
            float s2 = fmaf(sacc[nf][2], qscale, slope * (float)(key - qrow1));
            float s3 = fmaf(sacc[nf][3], qscale, slope * (float)(key + 1 - qrow1));
            if (maskt) {
                if (key > qrow0) s0 = -1e30f;
                if (key + 1 > qrow0) s1 = -1e30f;
                if (key > qrow1) s2 = -1e30f;
                if (key + 1 > qrow1) s3 = -1e30f;
            }
            sacc[nf][0] = s0; sacc[nf][1] = s1; sacc[nf][2] = s2; sacc[nf][3] = s3;
            mx0 = fmaxf(mx0, fmaxf(s0, s1));
            mx1 = fmaxf(mx1, fmaxf(s2, s3));
        }
        mx0 = fmaxf(mx0, __shfl_xor_sync(0xFFFFFFFFu, mx0, 1));
        mx0 = fmaxf(mx0, __shfl_xor_sync(0xFFFFFFFFu, mx0, 2));
        mx1 = fmaxf(mx1, __shfl_xor_sync(0xFFFFFFFFu, mx1, 1));
        mx1 = fmaxf(mx1, __shfl_xor_sync(0xFFFFFFFFu, mx1, 2));

        const float mn0 = fmaxf(m0, mx0);
        const float mn1 = fmaxf(m1, mx1);
        const float a0 = fexp2(m0 - mn0);
        const float a1 = fexp2(m1 - mn1);
        m0 = mn0; m1 = mn1;
        l0 *= a0; l1 *= a1;
#pragma unroll
        for (int nd = 0; nd < 8; ++nd) {
            oacc[nd][0] *= a0; oacc[nd][1] *= a0;
            oacc[nd][2] *= a1; oacc[nd][3] *= a1;
        }

        float rs0 = 0.f, rs1 = 0.f;
#pragma unroll
        for (int nf = 0; nf < 8; ++nf) {
            float p0 = fexp2(sacc[nf][0] - m0);
            float p1 = fexp2(sacc[nf][1] - m0);
            float p2 = fexp2(sacc[nf][2] - m1);
            float p3 = fexp2(sacc[nf][3] - m1);
            rs0 += p0 + p1; rs1 += p2 + p3;
            sacc[nf][0] = p0; sacc[nf][1] = p1; sacc[nf][2] = p2; sacc[nf][3] = p3;
        }
        rs0 += __shfl_xor_sync(0xFFFFFFFFu, rs0, 1);
        rs0 += __shfl_xor_sync(0xFFFFFFFFu, rs0, 2);
        rs1 += __shfl_xor_sync(0xFFFFFFFFu, rs1, 1);
        rs1 += __shfl_xor_sync(0xFFFFFFFFu, rs1, 2);
        l0 += rs0; l1 += rs1;

        // ---- pack P to A-frags (hi/lo) ----
        uint32_t pah[4][4], pal[4][4];
#pragma unroll
        for (int jp = 0; jp < 4; ++jp) {
            const int j0 = 2 * jp, j1 = 2 * jp + 1;
            float e[8] = {sacc[j0][0], sacc[j0][1], sacc[j0][2], sacc[j0][3],
                          sacc[j1][0], sacc[j1][1], sacc[j1][2], sacc[j1][3]};
            float eh[8], el[8];
#pragma unroll
            for (int x = 0; x < 8; ++x) {
                __nv_bfloat16 hb = __float2bfloat16(e[x]);
                eh[x] = __bfloat162float(hb);
                el[x] = e[x] - eh[x];
            }
            pah[jp][0] = pack2bf(eh[0], eh[1]); pah[jp][1] = pack2bf(eh[2], eh[3]);
            pah[jp][2] = pack2bf(eh[4], eh[5]); pah[jp][3] = pack2bf(eh[6], eh[7]);
            pal[jp][0] = pack2bf(el[0], el[1]); pal[jp][1] = pack2bf(el[2], el[3]);
            pal[jp][2] = pack2bf(el[4], el[5]); pal[jp][3] = pack2bf(el[6], el[7]);
        }

        // ---- O += P V (bf16x3) ----
#pragma unroll
        for (int jp = 0; jp < 4; ++jp) {
            uint32_t vbh[8][2], vbl[8][2];
#pragma unroll
            for (int p = 0; p < 4; ++p) {
                const int row = jp * 16 + rowoff;       // key rows
                const int cch = 2 * p + khalf;          // d 16B chunk
                const uint32_t off = row * 128 + ((cch ^ (row & 7)) << 4);
                uint32_t r[4];
                LDSM_X4_T(r, tb + 16384 + off);
                vbh[2 * p][0] = r[0]; vbh[2 * p][1] = r[1];
                vbh[2 * p + 1][0] = r[2]; vbh[2 * p + 1][1] = r[3];
                LDSM_X4_T(r, tb + 24576 + off);
                vbl[2 * p][0] = r[0]; vbl[2 * p][1] = r[1];
                vbl[2 * p + 1][0] = r[2]; vbl[2 * p + 1][1] = r[3];
            }
#pragma unroll
            for (int nd = 0; nd < 8; ++nd)
                MMA_BF16(oacc[nd], pah[jp], vbh[nd][0], vbh[nd][1]);
#pragma unroll
            for (int nd = 0; nd < 8; ++nd)
                MMA_BF16(oacc[nd], pal[jp], vbh[nd][0], vbh[nd][1]);
#pragma unroll
            for (int nd = 0; nd < 8; ++nd)
                MMA_BF16(oacc[nd], pah[jp], vbl[nd][0], vbl[nd][1]);
        }
        __syncthreads();
    }

    // ---- epilogue: O /= l, write bf16 hi/lo A operand for proj GEMM ----
    const float il0 = 1.0f / l0;
    const float il1 = 1.0f / l1;
    const size_t r0off = (size_t)(b * TT + qrow0) * CC + h * 64;
    const size_t r1off = (size_t)(b * TT + qrow1) * CC + h * 64;
#pragma unroll
    for (int nd = 0; nd < 8; ++nd) {
        const int cd = nd * 8 + 2 * t;
        float y0 = oacc[nd][0] * il0, y1 = oacc[nd][1] * il0;
        float y2 = oacc[nd][2] * il1, y3 = oacc[nd][3] * il1;
        __nv_bfloat16 h0, h1, l0b, l1b;
        bf16_split(y0, h0, l0b); bf16_split(y1, h1, l1b);
        *(__nv_bfloat162*)(g_ahi + r0off + cd) = __nv_bfloat162{h0, h1};
        *(__nv_bfloat162*)(g_alo + r0off + cd) = __nv_bfloat162{l0b, l1b};
        bf16_split(y2, h0, l0b); bf16_split(y3, h1, l1b);
        *(__nv_bfloat162*)(g_ahi + r1off + cd) = __nv_bfloat162{h0, h1};
        *(__nv_bfloat162*)(g_alo + r1off + cd) = __nv_bfloat162{l0b, l1b};
    }
}

// ---------------------------------------------------------------------------
// Harness entry
// ---------------------------------------------------------------------------
extern "C" void kernel_launch(void* const* d_in, const int* in_sizes, int n_in,
                              void* d_out, int out_size)
{
    const float* x      = (const float*)d_in[0];
    const float* W_attn = (const float*)d_in[1];
    const float* b_attn = (const float*)d_in[2];
    const float* W_proj = (const float*)d_in[3];
    const float* b_proj = (const float*)d_in[4];
    const float* temp   = (const float*)d_in[5];
    float* out = (float*)d_out;

    const int GEMM_SMEM = 2 * 65536;   // 131072
    const int ATTN_SMEM = 3 * 32768;   // 98304
    cudaFuncSetAttribute(hmma_gemm_kernel<3 * CC, 0>,
                         cudaFuncAttributeMaxDynamicSharedMemorySize, GEMM_SMEM);
    cudaFuncSetAttribute(hmma_gemm_kernel<CC, 1>,
                         cudaFuncAttributeMaxDynamicSharedMemorySize, GEMM_SMEM);
    cudaFuncSetAttribute(attn_mma_kernel,
                         cudaFuncAttributeMaxDynamicSharedMemorySize, ATTN_SMEM);

    // 0) precision-split inputs (bf16 hi/lo) + weight transposes
    split_x_kernel<<<(MM * CC / 4) / 256, 256>>>(x);
    tsplit_w_kernel<3 * CC, 0><<<dim3(3 * CC / 32, CC / 32), dim3(32, 8)>>>(W_attn);
    tsplit_w_kernel<CC, 1><<<dim3(CC / 32, CC / 32), dim3(32, 8)>>>(W_proj);

    // 1) QKV = x @ W_attn + b_attn  (bf16x3 HMMA, scatter to q/k/v hi/lo)
    hmma_gemm_kernel<3 * CC, 0><<<dim3(3 * CC / 128, MM / 128), 256, GEMM_SMEM>>>(
        b_attn, nullptr);

    // 2) tensor-core causal ALiBi attention -> bf16-split A for proj
    attn_mma_kernel<<<dim3(TT / 128, BB * HH), 256, ATTN_SMEM>>>(temp);

    // 3) out = att @ W_proj + b_proj  (bf16x3 HMMA)
    hmma_gemm_kernel<CC, 1><<<dim3(CC / 128, MM / 128), 256, GEMM_SMEM>>>(
        b_proj, out);
}

// round 9
// speedup vs baseline: 2.6691x; 1.0059x over previous
#include <cuda_runtime.h>
#include <cuda_bf16.h>
#include <cstdint>

// Problem constants
#define BB 2
#define TT 2048
#define CC 1024
#define HH 16
#define DD 64
#define MM (BB * TT)   // 4096 rows

// ---------------------------------------------------------------------------
// Device scratch (allocation-free per harness rules)
// ---------------------------------------------------------------------------
// q/k/v in bf16 hi/lo split, layout (b,h,t,d), d contiguous (128B rows)
__device__ __nv_bfloat16 g_qhi[(size_t)BB * HH * TT * DD];
__device__ __nv_bfloat16 g_qlo[(size_t)BB * HH * TT * DD];
__device__ __nv_bfloat16 g_khi[(size_t)BB * HH * TT * DD];
__device__ __nv_bfloat16 g_klo[(size_t)BB * HH * TT * DD];
__device__ __nv_bfloat16 g_vhi[(size_t)BB * HH * TT * DD];
__device__ __nv_bfloat16 g_vlo[(size_t)BB * HH * TT * DD];
// bf16 hi/lo precision splits for GEMM operands
__device__ __nv_bfloat16 g_xhi[(size_t)MM * CC];         // x        [M][K]
__device__ __nv_bfloat16 g_xlo[(size_t)MM * CC];
__device__ __nv_bfloat16 g_wahi[(size_t)3 * CC * CC];    // W_attn^T [N=3072][K=1024]
__device__ __nv_bfloat16 g_walo[(size_t)3 * CC * CC];
__device__ __nv_bfloat16 g_wphi[(size_t)CC * CC];        // W_proj^T [N=1024][K=1024]
__device__ __nv_bfloat16 g_wplo[(size_t)CC * CC];
__device__ __nv_bfloat16 g_ahi[(size_t)MM * CC];         // attention out [M][K]
__device__ __nv_bfloat16 g_alo[(size_t)MM * CC];

// ---------------------------------------------------------------------------
// PTX helpers (sm_80+ portable: cp.async / ldmatrix / mma.sync)
// ---------------------------------------------------------------------------
__device__ __forceinline__ uint32_t smem_to_u32(const void* smem_ptr) {
    uint32_t addr;
    asm("{ .reg .u64 tmp; cvta.to.shared.u64 tmp, %1; cvt.u32.u64 %0, tmp; }"
        : "=r"(addr) : "l"(smem_ptr));
    return addr;
}

__device__ __forceinline__ void cpasync16(uint32_t s, const void* g) {
    asm volatile("cp.async.cg.shared.global [%0], [%1], 16;" :: "r"(s), "l"(g) : "memory");
}

#define CP_COMMIT()  asm volatile("cp.async.commit_group;" ::: "memory")
#define CP_WAIT(n)   asm volatile("cp.async.wait_group %0;" :: "n"(n) : "memory")

#define LDSM_X4(r, addr) \
    asm volatile("ldmatrix.sync.aligned.m8n8.x4.shared.b16 {%0,%1,%2,%3}, [%4];" \
        : "=r"((r)[0]), "=r"((r)[1]), "=r"((r)[2]), "=r"((r)[3]) : "r"(addr))

#define LDSM_X4_T(r, addr) \
    asm volatile("ldmatrix.sync.aligned.m8n8.x4.trans.shared.b16 {%0,%1,%2,%3}, [%4];" \
        : "=r"((r)[0]), "=r"((r)[1]), "=r"((r)[2]), "=r"((r)[3]) : "r"(addr))

#define MMA_BF16(c, a, b0, b1) \
    asm volatile("mma.sync.aligned.m16n8k16.row.col.f32.bf16.bf16.f32 " \
        "{%0,%1,%2,%3}, {%4,%5,%6,%7}, {%8,%9}, {%0,%1,%2,%3};" \
        : "+f"((c)[0]), "+f"((c)[1]), "+f"((c)[2]), "+f"((c)[3]) \
        : "r"((a)[0]), "r"((a)[1]), "r"((a)[2]), "r"((a)[3]), "r"(b0), "r"(b1))

// fast exp2 on the FMA pipe (no MUFU). x clamped to >= -126; |err| < ~1e-7.
__device__ __forceinline__ float fexp2(float x) {
    x = fmaxf(x, -126.0f);
    float t = x + 12582912.0f;        // 1.5*2^23: RN rounds x to nearest int
    float r = t - 12582912.0f;
    float f = x - r;                  // f in [-0.5, 0.5]
    int e = (__float_as_int(t) + (127 - 0x400000)) << 23;  // 2^round(x) bits
    float p = 1.5353361883e-4f;
    p = fmaf(p, f, 1.3398874403e-3f);
    p = fmaf(p, f, 9.6184373577e-3f);
    p = fmaf(p, f, 5.5503324712e-2f);
    p = fmaf(p, f, 2.4022647914e-1f);
    p = fmaf(p, f, 6.9314720286e-1f);
    p = fmaf(p, f, 1.0f);
    return p * __int_as_float(e);
}

// ---------------------------------------------------------------------------
// Preprocessing: split fp32 -> (hi, lo) bf16
// ---------------------------------------------------------------------------
__device__ __forceinline__ void bf16_split(float v, __nv_bfloat16& h, __nv_bfloat16& l) {
    h = __float2bfloat16(v);
    l = __float2bfloat16(v - __bfloat162float(h));
}

__device__ __forceinline__ uint32_t pack2bf(float x, float y) {
    __nv_bfloat162 v{__float2bfloat16(x), __float2bfloat16(y)};
    return *(uint32_t*)&v;
}

__global__ __launch_bounds__(256) void split_x_kernel(const float* __restrict__ x) {
    size_t i = (size_t)blockIdx.x * 256 + threadIdx.x;  // over MM*CC/4 float4s
    float4 v = ((const float4*)x)[i];
    __nv_bfloat16 h0, h1, h2, h3, l0, l1, l2, l3;
    bf16_split(v.x, h0, l0); bf16_split(v.y, h1, l1);
    bf16_split(v.z, h2, l2); bf16_split(v.w, h3, l3);
    __nv_bfloat162* ph = (__nv_bfloat162*)(g_xhi + i * 4);
    __nv_bfloat162* pl = (__nv_bfloat162*)(g_xlo + i * 4);
    ph[0] = __nv_bfloat162{h0, h1}; ph[1] = __nv_bfloat162{h2, h3};
    pl[0] = __nv_bfloat162{l0, l1}; pl[1] = __nv_bfloat162{l2, l3};
}

// Transpose + split: W [K=1024][NN] fp32 -> Wt_hi/lo [NN][1024] bf16
template <int NN, int WHICH>
__global__ __launch_bounds__(256) void tsplit_w_kernel(const float* __restrict__ W) {
    __shared__ float tile[32][33];
    __nv_bfloat16* Whi = (WHICH == 0) ? g_wahi : g_wphi;
    __nv_bfloat16* Wlo = (WHICH == 0) ? g_walo : g_wplo;
    const int nb = blockIdx.x * 32;
    const int kb = blockIdx.y * 32;
    const int tx = threadIdx.x, ty = threadIdx.y;
#pragma unroll
    for (int r = 0; r < 4; ++r)
        tile[ty + r * 8][tx] = W[(size_t)(kb + ty + r * 8) * NN + nb + tx];
    __syncthreads();
#pragma unroll
    for (int r = 0; r < 4; ++r) {
        const int n = nb + ty + r * 8;
        const int k = kb + tx;
        float v = tile[tx][ty + r * 8];
        __nv_bfloat16 h, l;
        bf16_split(v, h, l);
        Whi[(size_t)n * 1024 + k] = h;
        Wlo[(size_t)n * 1024 + k] = l;
    }
}

// ---------------------------------------------------------------------------
// bf16x3 tensor-core GEMM (mma.sync.m16n8k16): C = A[M,K] @ Wt[N,K]^T + bias
// CTA tile 128x128. K-chunk 32 bf16 (64B rows, xor swizzle ch^((row>>1)&3)).
// 3-stage cp.async pipeline, ONE __syncthreads per iteration, 2 CTAs/SM.
// 8 warps as 2(m) x 4(n); warp tile 64x32 = 4 m-frags x 4 n-frags.
// 3 MMAs per accumulator per k16-step: Ahi*Bhi + Ahi*Blo + Alo*Bhi.
// MODE 0: A = x split, scatter into q/k/v bf16 hi/lo.  MODE 1: att -> Out.
// SMEM stage (32KB): Ahi@0, Alo@8192, Bhi@16384, Blo@24576 (8KB each).
// ---------------------------------------------------------------------------
template <int Ndim, int MODE>
__global__ __launch_bounds__(256, 2) void hmma_gemm_kernel(
    const float* __restrict__ bias, float* __restrict__ Out)
{
    extern __shared__ __align__(1024) char smem[];
    const uint32_t sbase = smem_to_u32(smem);
    const int tid = threadIdx.x;
    const int lane = tid & 31;
    const int wid = tid >> 5;
    const int wm = wid >> 2;   // 0..1
    const int wn = wid & 3;    // 0..3
    const int m0 = blockIdx.y * 128;
    const int n0 = blockIdx.x * 128;
    constexpr int KT = 32;     // 1024 / 32

    const __nv_bfloat16* Ahi = (MODE == 0) ? g_xhi : g_ahi;
    const __nv_bfloat16* Alo = (MODE == 0) ? g_xlo : g_alo;
    const __nv_bfloat16* Bhi = (MODE == 0) ? g_wahi : g_wphi;
    const __nv_bfloat16* Blo = (MODE == 0) ? g_walo : g_wplo;

    const char* gAh = (const char*)Ahi + (size_t)m0 * 2048;  // row = 1024 bf16 = 2048B
    const char* gAl = (const char*)Alo + (size_t)m0 * 2048;
    const char* gBh = (const char*)Bhi + (size_t)n0 * 2048;
    const char* gBl = (const char*)Blo + (size_t)n0 * 2048;

    float acc[4][4][4];
#pragma unroll
    for (int mf = 0; mf < 4; ++mf)
#pragma unroll
        for (int nf = 0; nf < 4; ++nf)
#pragma unroll
            for (int e = 0; e < 4; ++e) acc[mf][nf][e] = 0.f;

    // stage = 32KB; plane = 8KB = 512 x 16B chunks; 256 threads x 2 chunks
    auto issue = [&](int c) {
        const uint32_t tb = sbase + (uint32_t)(c % 3) * 32768;
        const int kb = c * 64;   // bytes along K (32 bf16)
#pragma unroll
        for (int i = 0; i < 2; ++i) {
            const int idx = tid + i * 256;
            const int row = idx >> 2;           // 0..127
            const int ch = idx & 3;             // 16B chunk in 64B row
            const uint32_t soff = row * 64 + ((ch ^ ((row >> 1) & 3)) << 4);
            const size_t goff = (size_t)row * 2048 + ch * 16 + kb;
            cpasync16(tb + 0     + soff, gAh + goff);
            cpasync16(tb + 8192  + soff, gAl + goff);
            cpasync16(tb + 16384 + soff, gBh + goff);
            cpasync16(tb + 24576 + soff, gBl + goff);
        }
        CP_COMMIT();
    };

    issue(0);
    issue(1);

    const int q8 = lane >> 3;
    const int iq = lane & 7;
    const int rowoff_a = ((q8 & 1) << 3) + iq;  // 0..15
    const int khalf = q8 >> 1;                  // 0/1: 16B chunk within k16

    for (int c = 0; c < KT; ++c) {
        CP_WAIT(1);          // chunk c resident (c+1 may be in flight)
        __syncthreads();
        if (c + 2 < KT) issue(c + 2);  // into buf (c+2)%3, consumed at iter c-1

        const uint32_t tb = sbase + (uint32_t)(c % 3) * 32768;
        const uint32_t aT = tb, alT = tb + 8192, bT = tb + 16384, blT = tb + 24576;

#pragma unroll
        for (int ks = 0; ks < 2; ++ks) {
            const int cch = ks * 2 + khalf;     // 16B chunk index 0..3
            uint32_t ah[4][4], al[4][4];
#pragma unroll
            for (int mf = 0; mf < 4; ++mf) {
                const int row = wm * 64 + mf * 16 + rowoff_a;
                const uint32_t off = row * 64 + ((cch ^ ((row >> 1) & 3)) << 4);
                LDSM_X4(ah[mf], aT + off);
                LDSM_X4(al[mf], alT + off);
            }
            uint32_t bh[4][2], bl[4][2];
#pragma unroll
            for (int np = 0; np < 2; ++np) {
                const int row = wn * 32 + np * 16 + rowoff_a;
                const uint32_t off = row * 64 + ((cch ^ ((row >> 1) & 3)) << 4);
                uint32_t r[4];
                LDSM_X4(r, bT + off);
                bh[2 * np][0] = r[0]; bh[2 * np][1] = r[2];
                bh[2 * np + 1][0] = r[1]; bh[2 * np + 1][1] = r[3];
                LDSM_X4(r, blT + off);
                bl[2 * np][0] = r[0]; bl[2 * np][1] = r[2];
                bl[2 * np + 1][0] = r[1]; bl[2 * np + 1][1] = r[3];
            }
#pragma unroll
            for (int mf = 0; mf < 4; ++mf)
#pragma unroll
                for (int nf = 0; nf < 4; ++nf)
                    MMA_BF16(acc[mf][nf], ah[mf], bh[nf][0], bh[nf][1]);
#pragma unroll
            for (int mf = 0; mf < 4; ++mf)
#pragma unroll
                for (int nf = 0; nf < 4; ++nf)
                    MMA_BF16(acc[mf][nf], ah[mf], bl[nf][0], bl[nf][1]);
#pragma unroll
            for (int mf = 0; mf < 4; ++mf)
#pragma unroll
                for (int nf = 0; nf < 4; ++nf)
                    MMA_BF16(acc[mf][nf], al[mf], bh[nf][0], bh[nf][1]);
        }
    }

    // Epilogue. Frag map: c0,c1 -> (row g, cols 2t,2t+1); c2,c3 -> row g+8.
    const int g = lane >> 2, t = lane & 3;
#pragma unroll
    for (int mf = 0; mf < 4; ++mf) {
        const int r_lo = m0 + wm * 64 + mf * 16 + g;
#pragma unroll
        for (int nf = 0; nf < 4; ++nf) {
            const int col = n0 + wn * 32 + nf * 8 + 2 * t;
            const float b0 = bias[col], b1 = bias[col + 1];
            float v00 = acc[mf][nf][0] + b0, v01 = acc[mf][nf][1] + b1;
            float v10 = acc[mf][nf][2] + b0, v11 = acc[mf][nf][3] + b1;
            if (MODE == 0) {
                // split into bf16 hi/lo and scatter to q/k/v (b,h,t,d)
                const int which = col >> 10;
                const int ci = col & 1023;
                const int hh = ci >> 6;
                const int dd = ci & 63;
                __nv_bfloat16* dh = (which == 0) ? g_qhi : ((which == 1) ? g_khi : g_vhi);
                __nv_bfloat16* dl = (which == 0) ? g_qlo : ((which == 1) ? g_klo : g_vlo);
                __nv_bfloat16 h0, h1, l0, l1;
                const int b_lo = r_lo >> 11, t_lo = r_lo & 2047;
                size_t off = (((size_t)b_lo * HH + hh) * TT + t_lo) * DD + dd;
                bf16_split(v00, h0, l0); bf16_split(v01, h1, l1);
                *(__nv_bfloat162*)(dh + off) = __nv_bfloat162{h0, h1};
                *(__nv_bfloat162*)(dl + off) = __nv_bfloat162{l0, l1};
                const int r_hi = r_lo + 8;
                const int b_hi = r_hi >> 11, t_hi = r_hi & 2047;
                off = (((size_t)b_hi * HH + hh) * TT + t_hi) * DD + dd;
                bf16_split(v10, h0, l0); bf16_split(v11, h1, l1);
                *(__nv_bfloat162*)(dh + off) = __nv_bfloat162{h0, h1};
                *(__nv_bfloat162*)(dl + off) = __nv_bfloat162{l0, l1};
            } else {
                *(float2*)(Out + (size_t)r_lo * Ndim + col) = float2{v00, v01};
                *(float2*)(Out + (size_t)(r_lo + 8) * Ndim + col) = float2{v10, v11};
            }
        }
    }
}

// ---------------------------------------------------------------------------
// Tensor-core flash attention with ALiBi + temperature (unchanged from R7).
// CTA: 128 q-rows of one (b,h). 8 warps x m16. K/V tiles of 64 keys,
// double-buffered cp.async. bf16x3 on QK^T and P*V. exp2 via FMA polynomial.
// SMEM: Q stage 32KB @0 (hi 16K, lo 16K); buffers @32768 + buf*32768:
//       Khi@0 Klo@8192 Vhi@16384 Vlo@24576 (8KB each: 64 rows x 128B).
// ---------------------------------------------------------------------------
__global__ __launch_bounds__(256) void attn_mma_kernel(const float* __restrict__ temp)
{
    extern __shared__ __align__(1024) char smem[];
    const uint32_t sb = smem_to_u32(smem);
    const int tid = threadIdx.x;
    const int lane = tid & 31;
    const int wid = tid >> 5;
    const int bh = blockIdx.y;
    const int qt = (int)gridDim.x - 1 - blockIdx.x;   // heavy tiles first
    const int b = bh >> 4;
    const int h = bh & 15;

    const float qscale = 0.125f * (1.0f / temp[0]) * 1.44269504088896340736f;
    const float slope = exp2f(-0.5f * (float)(h + 1)) * 1.44269504088896340736f;

    const int q8 = lane >> 3;
    const int iq = lane & 7;
    const int rowoff = ((q8 & 1) << 3) + iq;   // 0..15
    const int khalf = q8 >> 1;                 // 0/1
    const int g = lane >> 2, t = lane & 3;

    const char* gQh = (const char*)g_qhi + ((size_t)bh * TT + qt * 128) * 128;
    const char* gQl = (const char*)g_qlo + ((size_t)bh * TT + qt * 128) * 128;
    const char* gKh = (const char*)g_khi + (size_t)bh * TT * 128;
    const char* gKl = (const char*)g_klo + (size_t)bh * TT * 128;
    const char* gVh = (const char*)g_vhi + (size_t)bh * TT * 128;
    const char* gVl = (const char*)g_vlo + (size_t)bh * TT * 128;

    const int nkt = 2 * qt + 2;  // number of 64-key tiles (causal)

    // ---- stage Q (group 0) ----
#pragma unroll
    for (int i = 0; i < 4; ++i) {
        const int idx = tid + i * 256;
        const int row = idx >> 3;
        const int ch = idx & 7;
        const uint32_t soff = row * 128 + ((ch ^ (row & 7)) << 4);
        const size_t goff = (size_t)row * 128 + ch * 16;
        cpasync16(sb + 0     + soff, gQh + goff);
        cpasync16(sb + 16384 + soff, gQl + goff);
    }
    CP_COMMIT();

    auto issue_kv = [&](int kt) {
        const uint32_t tb = sb + 32768 + (uint32_t)(kt & 1) * 32768;
        const size_t kbase = (size_t)kt * 64 * 128;
#pragma unroll
        for (int i = 0; i < 2; ++i) {
            const int idx = tid + i * 256;
            const int row = idx >> 3;
            const int ch = idx & 7;
            const uint32_t soff = row * 128 + ((ch ^ (row & 7)) << 4);
            const size_t goff = kbase + (size_t)row * 128 + ch * 16;
            cpasync16(tb + 0     + soff, gKh + goff);
            cpasync16(tb + 8192  + soff, gKl + goff);
            cpasync16(tb + 16384 + soff, gVh + goff);
            cpasync16(tb + 24576 + soff, gVl + goff);
        }
        CP_COMMIT();
    };

    issue_kv(0);
    CP_WAIT(1);          // Q complete (kv0 may be in flight)
    __syncthreads();

    // ---- Q fragments (resident) ----
    uint32_t qh[4][4], ql[4][4];
#pragma unroll
    for (int ks = 0; ks < 4; ++ks) {
        const int row = wid * 16 + rowoff;
        const int cch = ks * 2 + khalf;
        const uint32_t off = row * 128 + ((cch ^ (row & 7)) << 4);
        LDSM_X4(qh[ks], sb + off);
        LDSM_X4(ql[ks], sb + 16384 + off);
    }

    float oacc[8][4];
#pragma unroll
    for (int nd = 0; nd < 8; ++nd)
#pragma unroll
        for (int e = 0; e < 4; ++e) oacc[nd][e] = 0.f;
    float m0 = -1e30f, m1 = -1e30f, l0 = 0.f, l1 = 0.f;

    const int qrow0 = qt * 128 + wid * 16 + g;
    const int qrow1 = qrow0 + 8;

    for (int kt = 0; kt < nkt; ++kt) {
        if (kt + 1 < nkt) { issue_kv(kt + 1); CP_WAIT(1); }
        else              { CP_WAIT(0); }
        __syncthreads();

        const uint32_t tb = sb + 32768 + (uint32_t)(kt & 1) * 32768;

        // ---- S = Q K^T (bf16x3) ----
        float sacc[8][4];
#pragma unroll
        for (int nf = 0; nf < 8; ++nf)
#pragma unroll
            for (int e = 0; e < 4; ++e) sacc[nf][e] = 0.f;

#pragma unroll
        for (int ks = 0; ks < 4; ++ks) {
            const int cch = ks * 2 + khalf;
            uint32_t kbh[8][2], kbl[8][2];
#pragma unroll
            for (int np = 0; np < 4; ++np) {
                const int row = np * 16 + rowoff;
                const uint32_t off = row * 128 + ((cch ^ (row & 7)) << 4);
                uint32_t r[4];
                LDSM_X4(r, tb + off);
                kbh[2 * np][0] = r[0]; kbh[2 * np][1] = r[2];
                kbh[2 * np + 1][0] = r[1]; kbh[2 * np + 1][1] = r[3];
                LDSM_X4(r, tb + 8192 + off);
                kbl[2 * np][0] = r[0]; kbl[2 * np][1] = r[2];
                kbl[2 * np + 1][0] = r[1]; kbl[2 * np + 1][1] = r[3];
            }
#pragma unroll
            for (int nf = 0; nf < 8; ++nf)
                MMA_BF16(sacc[nf], qh[ks], kbh[nf][0], kbh[nf][1]);
#pragma unroll
            for (int nf = 0; nf < 8; ++nf)
                MMA_BF16(sacc[nf], qh[ks], kbl[nf][0], kbl[nf][1]);
#pragma unroll
            for (int nf = 0; nf < 8; ++nf)
                MMA_BF16(sacc[nf], ql[ks], kbh[nf][0], kbh[nf][1]);
        }

        // ---- softmax (online) ----
        const bool maskt = (kt >= 2 * qt);
        float mx0 = -1e30f, mx1 = -1e30f;
#pragma unroll
        for (int nf = 0; nf < 8; ++nf) {
            const int key = kt * 64 + nf * 8 + 2 * t;
            float s0 = fmaf(sacc[nf][0], qscale, slope * (float)(key - qrow0));
            float s1 = fmaf(sacc[nf][1], qscale, slope * (float)(key + 1 - qrow0));
            float s2 = fmaf(sacc[nf][2], qscale, slope * (float)(key - qrow1));
            float s3 = fmaf(sacc[nf][3], qscale, slope * (float)(key + 1 - qrow1));
            if (maskt) {
                if (key > qrow0) s0 = -1e30f;
                if (key + 1 > qrow0) s1 = -1e30f;
                if (key > qrow1) s2 = -1e30f;
                if (key + 1 > qrow1) s3 = -1e30f;
            }
            sacc[nf][0] = s0; sacc[nf][1] = s1; sacc[nf][2] = s2; sacc[nf][3] = s3;
            mx0 = fmaxf(mx0, fmaxf(s0, s1));
            mx1 = fmaxf(mx1, fmaxf(s2, s3));
        }
        mx0 = fmaxf(mx0, __shfl_xor_sync(0xFFFFFFFFu, mx0, 1));
        mx0 = fmaxf(mx0, __shfl_xor_sync(0xFFFFFFFFu, mx0, 2));
        mx1 = fmaxf(mx1, __shfl_xor_sync(0xFFFFFFFFu, mx1, 1));
        mx1 = fmaxf(mx1, __shfl_xor_sync(0xFFFFFFFFu, mx1, 2));

        const float mn0 = fmaxf(m0, mx0);
        const float mn1 = fmaxf(m1, mx1);
        const float a0 = fexp2(m0 - mn0);
        const float a1 = fexp2(m1 - mn1);
        m0 = mn0; m1 = mn1;
        l0 *= a0; l1 *= a1;
#pragma unroll
        for (int nd = 0; nd < 8; ++nd) {
            oacc[nd][0] *= a0; oacc[nd][1] *= a0;
            oacc[nd][2] *= a1; oacc[nd][3] *= a1;
        }

        float rs0 = 0.f, rs1 = 0.f;
#pragma unroll
        for (int nf = 0; nf < 8; ++nf) {
            float p0 = fexp2(sacc[nf][0] - m0);
            float p1 = fexp2(sacc[nf][1] - m0);
            float p2 = fexp2(sacc[nf][2] - m1);
            float p3 = fexp2(sacc[nf][3] - m1);
            rs0 += p0 + p1; rs1 += p2 + p3;
            sacc[nf][0] = p0; sacc[nf][1] = p1; sacc[nf][2] = p2; sacc[nf][3] = p3;
        }
        rs0 += __shfl_xor_sync(0xFFFFFFFFu, rs0, 1);
        rs0 += __shfl_xor_sync(0xFFFFFFFFu, rs0, 2);
        rs1 += __shfl_xor_sync(0xFFFFFFFFu, rs1, 1);
        rs1 += __shfl_xor_sync(0xFFFFFFFFu, rs1, 2);
        l0 += rs0; l1 += rs1;

        // ---- pack P to A-frags (hi/lo) ----
        uint32_t pah[4][4], pal[4][4];
#pragma unroll
        for (int jp = 0; jp < 4; ++jp) {
            const int j0 = 2 * jp, j1 = 2 * jp + 1;
            float e[8] = {sacc[j0][0], sacc[j0][1], sacc[j0][2], sacc[j0][3],
                          sacc[j1][0], sacc[j1][1], sacc[j1][2], sacc[j1][3]};
            float eh[8], el[8];
#pragma unroll
            for (int x = 0; x < 8; ++x) {
                __nv_bfloat16 hb = __float2bfloat16(e[x]);
                eh[x] = __bfloat162float(hb);
                el[x] = e[x] - eh[x];
            }
            pah[jp][0] = pack2bf(eh[0], eh[1]); pah[jp][1] = pack2bf(eh[2], eh[3]);
            pah[jp][2] = pack2bf(eh[4], eh[5]); pah[jp][3] = pack2bf(eh[6], eh[7]);
            pal[jp][0] = pack2bf(el[0], el[1]); pal[jp][1] = pack2bf(el[2], el[3]);
            pal[jp][2] = pack2bf(el[4], el[5]); pal[jp][3] = pack2bf(el[6], el[7]);
        }

        // ---- O += P V (bf16x3) ----
#pragma unroll
        for (int jp = 0; jp < 4; ++jp) {
            uint32_t vbh[8][2], vbl[8][2];
#pragma unroll
            for (int p = 0; p < 4; ++p) {
                const int row = jp * 16 + rowoff;       // key rows
                const int cch = 2 * p + khalf;          // d 16B chunk
                const uint32_t off = row * 128 + ((cch ^ (row & 7)) << 4);
                uint32_t r[4];
                LDSM_X4_T(r, tb + 16384 + off);
                vbh[2 * p][0] = r[0]; vbh[2 * p][1] = r[1];
                vbh[2 * p + 1][0] = r[2]; vbh[2 * p + 1][1] = r[3];
                LDSM_X4_T(r, tb + 24576 + off);
                vbl[2 * p][0] = r[0]; vbl[2 * p][1] = r[1];
                vbl[2 * p + 1][0] = r[2]; vbl[2 * p + 1][1] = r[3];
            }
#pragma unroll
            for (int nd = 0; nd < 8; ++nd)
                MMA_BF16(oacc[nd], pah[jp], vbh[nd][0], vbh[nd][1]);
#pragma unroll
            for (int nd = 0; nd < 8; ++nd)
                MMA_BF16(oacc[nd], pal[jp], vbh[nd][0], vbh[nd][1]);
#pragma unroll
            for (int nd = 0; nd < 8; ++nd)
                MMA_BF16(oacc[nd], pah[jp], vbl[nd][0], vbl[nd][1]);
        }
        __syncthreads();
    }

    // ---- epilogue: O /= l, write bf16 hi/lo A operand for proj GEMM ----
    const float il0 = 1.0f / l0;
    const float il1 = 1.0f / l1;
    const size_t r0off = (size_t)(b * TT + qrow0) * CC + h * 64;
    const size_t r1off = (size_t)(b * TT + qrow1) * CC + h * 64;
#pragma unroll
    for (int nd = 0; nd < 8; ++nd) {
        const int cd = nd * 8 + 2 * t;
        float y0 = oacc[nd][0] * il0, y1 = oacc[nd][1] * il0;
        float y2 = oacc[nd][2] * il1, y3 = oacc[nd][3] * il1;
        __nv_bfloat16 h0, h1, l0b, l1b;
        bf16_split(y0, h0, l0b); bf16_split(y1, h1, l1b);
        *(__nv_bfloat162*)(g_ahi + r0off + cd) = __nv_bfloat162{h0, h1};
        *(__nv_bfloat162*)(g_alo + r0off + cd) = __nv_bfloat162{l0b, l1b};
        bf16_split(y2, h0, l0b); bf16_split(y3, h1, l1b);
        *(__nv_bfloat162*)(g_ahi + r1off + cd) = __nv_bfloat162{h0, h1};
        *(__nv_bfloat162*)(g_alo + r1off + cd) = __nv_bfloat162{l0b, l1b};
    }
}

// ---------------------------------------------------------------------------
// Harness entry
// ---------------------------------------------------------------------------
extern "C" void kernel_launch(void* const* d_in, const int* in_sizes, int n_in,
                              void* d_out, int out_size)
{
    const float* x      = (const float*)d_in[0];
    const float* W_attn = (const float*)d_in[1];
    const float* b_attn = (const float*)d_in[2];
    const float* W_proj = (const float*)d_in[3];
    const float* b_proj = (const float*)d_in[4];
    const float* temp   = (const float*)d_in[5];
    float* out = (float*)d_out;

    const int GEMM_SMEM = 3 * 32768;   // 98304 (2 CTAs/SM)
    const int ATTN_SMEM = 3 * 32768;   // 98304
    cudaFuncSetAttribute(hmma_gemm_kernel<3 * CC, 0>,
                         cudaFuncAttributeMaxDynamicSharedMemorySize, GEMM_SMEM);
    cudaFuncSetAttribute(hmma_gemm_kernel<CC, 1>,
                         cudaFuncAttributeMaxDynamicSharedMemorySize, GEMM_SMEM);
    cudaFuncSetAttribute(attn_mma_kernel,
                         cudaFuncAttributeMaxDynamicSharedMemorySize, ATTN_SMEM);

    // 0) precision-split inputs (bf16 hi/lo) + weight transposes
    split_x_kernel<<<(MM * CC / 4) / 256, 256>>>(x);
    tsplit_w_kernel<3 * CC, 0><<<dim3(3 * CC / 32, CC / 32), dim3(32, 8)>>>(W_attn);
    tsplit_w_kernel<CC, 1><<<dim3(CC / 32, CC / 32), dim3(32, 8)>>>(W_proj);

    // 1) QKV = x @ W_attn + b_attn  (bf16x3 HMMA, scatter to q/k/v hi/lo)
    hmma_gemm_kernel<3 * CC, 0><<<dim3(3 * CC / 128, MM / 128), 256, GEMM_SMEM>>>(
        b_attn, nullptr);

    // 2) tensor-core causal ALiBi attention -> bf16-split A for proj
    attn_mma_kernel<<<dim3(TT / 128, BB * HH), 256, ATTN_SMEM>>>(temp);

    // 3) out = att @ W_proj + b_proj  (bf16x3 HMMA)
    hmma_gemm_kernel<CC, 1><<<dim3(CC / 128, MM / 128), 256, GEMM_SMEM>>>(
        b_proj, out);
}